// round 9
// baseline (speedup 1.0000x reference)
#include <cuda_runtime.h>
#include <cuda_bf16.h>
#include <math.h>

#define H 128
#define IN_SZ 64
#define MAX_NODES 50000

// ---------------- scratch (no allocations allowed) ----------------
__device__ float g_A[(size_t)MAX_NODES * H];         // h @ W_eg[:, :128].T + b_eg
__device__ float g_B[(size_t)MAX_NODES * H];         // h @ W_eg[:, 128:].T
__device__ float g_up[(size_t)MAX_NODES * H];        // upstream_q accumulator
__device__ float g_gates[(size_t)MAX_NODES * 4 * H]; // pre-activation LSTM gates

__device__ __forceinline__ float sigmoidf_(float x) {
    return 1.0f / (1.0f + __expf(-x));
}

// =====================================================================
// 128x128x8 SGEMM tile machinery: 256 threads, 8x8 per thread.
// Double-buffered smem (1 __syncthreads per k-tile). Rows padded to 132
// floats (528 B: 16B-aligned for LDS.128; k-rows shift banks -> no STS
// conflicts).
// =====================================================================
#define TBM 128
#define TBN 128
#define TBK 8
#define TPAD 132

#define GEMM_FMA_BLOCK(AsBuf, WsBuf)                                        \
    _Pragma("unroll")                                                       \
    for (int k = 0; k < TBK; ++k) {                                         \
        float4 a0 = *(const float4*)&AsBuf[k][ty * 4];                      \
        float4 a1 = *(const float4*)&AsBuf[k][64 + ty * 4];                 \
        float4 b0 = *(const float4*)&WsBuf[k][tx * 4];                      \
        float4 b1 = *(const float4*)&WsBuf[k][64 + tx * 4];                 \
        const float av[8] = {a0.x, a0.y, a0.z, a0.w, a1.x, a1.y, a1.z, a1.w}; \
        const float bv[8] = {b0.x, b0.y, b0.z, b0.w, b1.x, b1.y, b1.z, b1.w}; \
        _Pragma("unroll")                                                   \
        for (int i = 0; i < 8; ++i)                                         \
            _Pragma("unroll")                                               \
            for (int j = 0; j < 8; ++j)                                     \
                acc[i][j] += av[i] * bv[j];                                 \
    }

#define STORE_TILE(AsBuf, WsBuf)                                            \
    do {                                                                    \
        AsBuf[lcg + 0][lrow] = va.x;                                        \
        AsBuf[lcg + 1][lrow] = va.y;                                        \
        AsBuf[lcg + 2][lrow] = va.z;                                        \
        AsBuf[lcg + 3][lrow] = va.w;                                        \
        WsBuf[lcg + 0][lrow] = vw.x;                                        \
        WsBuf[lcg + 1][lrow] = vw.y;                                        \
        WsBuf[lcg + 2][lrow] = vw.z;                                        \
        WsBuf[lcg + 3][lrow] = vw.w;                                        \
    } while (0)

// ---------------- GEMM 1: [q | A | B] = h @ [Wq | W1 | W2].T ----------------
// M x 384, K = 128. blockIdx.y selects the 128-col slab: 0->q, 1->A, 2->B.
__global__ __launch_bounds__(256, 2)
void gemm_qab(const float* __restrict__ h,
              const float* __restrict__ Wq,
              const float* __restrict__ bq,
              const float* __restrict__ Weg,
              const float* __restrict__ beg,
              float* __restrict__ qout,
              int M) {
    __shared__ float As[2][TBK][TPAD];
    __shared__ float Ws[2][TBK][TPAD];

    const int t    = threadIdx.x;
    const int tx   = t & 15;          // 0..15
    const int ty   = t >> 4;          // 0..15
    const int row0 = blockIdx.x * TBM;
    const int slab = blockIdx.y;      // 0,1,2

    const int lrow = t >> 1;          // 0..127
    const int lcg  = (t & 1) * 4;     // 0 or 4
    const int grow = row0 + lrow;
    const bool rowok = (grow < M);

    const float* wrow;
    if (slab == 0)      wrow = Wq  + (size_t)lrow * H;
    else if (slab == 1) wrow = Weg + (size_t)lrow * 256;
    else                wrow = Weg + (size_t)lrow * 256 + 128;

    float acc[8][8] = {};

    // tile 0 -> buffer 0
    float4 va = make_float4(0.f, 0.f, 0.f, 0.f);
    if (rowok) va = *(const float4*)&h[(size_t)grow * H + lcg];
    float4 vw = *(const float4*)&wrow[lcg];
    STORE_TILE(As[0], Ws[0]);
    __syncthreads();

    int buf = 0;
    const int NK = H / TBK;
    for (int kt = 0; kt < NK; ++kt) {
        const bool has_next = (kt + 1 < NK);
        if (has_next) {
            const int kk = (kt + 1) * TBK + lcg;
            if (rowok) va = *(const float4*)&h[(size_t)grow * H + kk];
            vw = *(const float4*)&wrow[kk];
        }

        if (buf == 0) { GEMM_FMA_BLOCK(As[0], Ws[0]); }
        else          { GEMM_FMA_BLOCK(As[1], Ws[1]); }

        if (has_next) {
            if (buf == 0) STORE_TILE(As[1], Ws[1]);
            else          STORE_TILE(As[0], Ws[0]);
            __syncthreads();
            buf ^= 1;
        }
    }

    // --- epilogue ---
    #pragma unroll
    for (int i = 0; i < 8; ++i) {
        const int r = row0 + ((i < 4) ? (ty * 4 + i) : (64 + ty * 4 + i - 4));
        if (r >= M) continue;
        #pragma unroll
        for (int j = 0; j < 8; ++j) {
            const int n = (j < 4) ? (tx * 4 + j) : (64 + tx * 4 + j - 4);
            const float v = acc[i][j];
            if (slab == 0)      qout[(size_t)r * H + n] = v + bq[n];
            else if (slab == 1) g_A[(size_t)r * H + n]  = v + beg[n];
            else                g_B[(size_t)r * H + n]  = v;
        }
    }
}

// ---------------- GEMM 2: gates = x @ W_ih.T + b_ih + h @ W_hh.T -------------
// M x 512, K = 192 (first 64 from x/W_ih, next 128 from h/W_hh).
__global__ __launch_bounds__(256, 2)
void gemm_gates(const float* __restrict__ x,
                const float* __restrict__ h,
                const float* __restrict__ Wih,
                const float* __restrict__ bih,
                const float* __restrict__ Whh,
                int M) {
    __shared__ float As[2][TBK][TPAD];
    __shared__ float Ws[2][TBK][TPAD];

    const int t    = threadIdx.x;
    const int tx   = t & 15;
    const int ty   = t >> 4;
    const int row0 = blockIdx.x * TBM;
    const int n0   = blockIdx.y * TBN;   // 0..511

    const int lrow = t >> 1;
    const int lcg  = (t & 1) * 4;
    const int grow = row0 + lrow;
    const int gn   = n0 + lrow;
    const bool rowok = (grow < M);

    float acc[8][8] = {};

    // tile 0 (kk = lcg < 64 -> x / Wih region)
    float4 va = make_float4(0.f, 0.f, 0.f, 0.f);
    if (rowok) va = *(const float4*)&x[(size_t)grow * IN_SZ + lcg];
    float4 vw = *(const float4*)&Wih[(size_t)gn * IN_SZ + lcg];
    STORE_TILE(As[0], Ws[0]);
    __syncthreads();

    int buf = 0;
    const int NK = (IN_SZ + H) / TBK;
    for (int kt = 0; kt < NK; ++kt) {
        const bool has_next = (kt + 1 < NK);
        if (has_next) {
            const int kk = (kt + 1) * TBK + lcg;  // multiple of 4; never straddles 64
            if (rowok) {
                if (kk < IN_SZ) va = *(const float4*)&x[(size_t)grow * IN_SZ + kk];
                else            va = *(const float4*)&h[(size_t)grow * H + (kk - IN_SZ)];
            }
            if (kk < IN_SZ) vw = *(const float4*)&Wih[(size_t)gn * IN_SZ + kk];
            else            vw = *(const float4*)&Whh[(size_t)gn * H + (kk - IN_SZ)];
        }

        if (buf == 0) { GEMM_FMA_BLOCK(As[0], Ws[0]); }
        else          { GEMM_FMA_BLOCK(As[1], Ws[1]); }

        if (has_next) {
            if (buf == 0) STORE_TILE(As[1], Ws[1]);
            else          STORE_TILE(As[0], Ws[0]);
            __syncthreads();
            buf ^= 1;
        }
    }

    #pragma unroll
    for (int i = 0; i < 8; ++i) {
        const int r = row0 + ((i < 4) ? (ty * 4 + i) : (64 + ty * 4 + i - 4));
        if (r >= M) continue;
        #pragma unroll
        for (int j = 0; j < 8; ++j) {
            const int n = n0 + ((j < 4) ? (tx * 4 + j) : (64 + tx * 4 + j - 4));
            g_gates[(size_t)r * (4 * H) + n] = acc[i][j] + bih[n];
        }
    }
}

// ---------------- zero upstream accumulator (vectorized) ----------------
__global__ void zero_up(int n4) {  // n4 = M*H/4
    int idx = blockIdx.x * blockDim.x + threadIdx.x;
    if (idx < n4) ((float4*)g_up)[idx] = make_float4(0.f, 0.f, 0.f, 0.f);
}

// ---------------- edge kernel: gate, message, vectorized scatter-add ---------
// One warp per edge; each lane handles 4 channels via float4.
__global__ void edge_kernel(const int* __restrict__ snd,
                            const int* __restrict__ rcv,
                            const float* __restrict__ ew,
                            const float* __restrict__ q,
                            int E) {
    const int idx  = blockIdx.x * blockDim.x + threadIdx.x;
    const int e    = idx >> 5;
    const int lane = idx & 31;
    if (e >= E) return;

    const int s   = __ldg(&snd[e]);
    const int r   = __ldg(&rcv[e]);
    const float w = __ldg(&ew[e]);

    const size_t so = (size_t)s * 32 + lane;   // in float4 units
    const size_t ro = (size_t)r * 32 + lane;

    const float4 a  = ((const float4*)g_A)[so];
    const float4 b  = ((const float4*)g_B)[ro];
    const float4 qv = ((const float4*)q)[so];

    float4 m;
    m.x = qv.x * w * sigmoidf_(a.x + b.x);
    m.y = qv.y * w * sigmoidf_(a.y + b.y);
    m.z = qv.z * w * sigmoidf_(a.z + b.z);
    m.w = qv.w * w * sigmoidf_(a.w + b.w);

    float* dst = g_up + ro * 4;
#if defined(__CUDA_ARCH__) && (__CUDA_ARCH__ >= 900)
    asm volatile("red.global.add.v4.f32 [%0], {%1, %2, %3, %4};"
                 :: "l"(dst), "f"(m.x), "f"(m.y), "f"(m.z), "f"(m.w)
                 : "memory");
#else
    atomicAdd(dst + 0, m.x);
    atomicAdd(dst + 1, m.y);
    atomicAdd(dst + 2, m.z);
    atomicAdd(dst + 3, m.w);
#endif
}

// ---------------- final LSTM elementwise (vectorized) ----------------
__global__ void lstm_kernel(const float* __restrict__ c_prev,
                            float* __restrict__ h_out,
                            float* __restrict__ c_out,
                            int n4) {  // n4 = M*H/4
    int idx = blockIdx.x * blockDim.x + threadIdx.x;
    if (idx >= n4) return;
    const int node = idx >> 5;       // 32 float4s per node
    const int c4   = idx & 31;
    const size_t gbase = (size_t)node * 128;  // 4H floats = 128 float4s
    const float4 gi = ((const float4*)g_gates)[gbase + c4];
    const float4 gf = ((const float4*)g_gates)[gbase + 32 + c4];
    const float4 gg = ((const float4*)g_gates)[gbase + 64 + c4];
    const float4 go = ((const float4*)g_gates)[gbase + 96 + c4];
    const float4 cp = ((const float4*)c_prev)[idx];
    const float4 up = ((const float4*)g_up)[idx];

    float4 hn, cn;
    {
        float i = sigmoidf_(gi.x), f = sigmoidf_(gf.x), g = tanhf(gg.x), o = sigmoidf_(go.x);
        cn.x = f * (cp.x + up.x) + i * g;  hn.x = o * tanhf(cn.x);
    }
    {
        float i = sigmoidf_(gi.y), f = sigmoidf_(gf.y), g = tanhf(gg.y), o = sigmoidf_(go.y);
        cn.y = f * (cp.y + up.y) + i * g;  hn.y = o * tanhf(cn.y);
    }
    {
        float i = sigmoidf_(gi.z), f = sigmoidf_(gf.z), g = tanhf(gg.z), o = sigmoidf_(go.z);
        cn.z = f * (cp.z + up.z) + i * g;  hn.z = o * tanhf(cn.z);
    }
    {
        float i = sigmoidf_(gi.w), f = sigmoidf_(gf.w), g = tanhf(gg.w), o = sigmoidf_(go.w);
        cn.w = f * (cp.w + up.w) + i * g;  hn.w = o * tanhf(cn.w);
    }
    ((float4*)h_out)[idx] = hn;
    ((float4*)c_out)[idx] = cn;
}

// ---------------- launch ----------------
extern "C" void kernel_launch(void* const* d_in, const int* in_sizes, int n_in,
                              void* d_out, int out_size) {
    const float* x   = (const float*)d_in[0];
    const float* h   = (const float*)d_in[1];
    const float* cp  = (const float*)d_in[2];
    const int*   snd = (const int*)d_in[3];
    const int*   rcv = (const int*)d_in[4];
    const float* ew  = (const float*)d_in[5];
    // d_in[6] = num_nodes (scalar, unused; derived from sizes)
    const float* Wih = (const float*)d_in[7];
    const float* bih = (const float*)d_in[8];
    const float* Whh = (const float*)d_in[9];
    const float* Wq  = (const float*)d_in[10];
    const float* bq  = (const float*)d_in[11];
    const float* Weg = (const float*)d_in[12];
    const float* beg = (const float*)d_in[13];

    const int M = in_sizes[1] / H;       // 50000
    const int E = in_sizes[3];           // 800000

    float* out   = (float*)d_out;
    float* h_out = out;
    float* c_out = out + (size_t)M * H;
    float* q_out = out + (size_t)2 * M * H;

    const int nMH  = M * H;
    const int nMH4 = nMH / 4;

    // node GEMMs (must precede edge/lstm)
    dim3 g1((M + TBM - 1) / TBM, 3);
    gemm_qab<<<g1, 256>>>(h, Wq, bq, Weg, beg, q_out, M);

    dim3 g2((M + TBM - 1) / TBM, 4);
    gemm_gates<<<g2, 256>>>(x, h, Wih, bih, Whh, M);

    zero_up<<<(nMH4 + 255) / 256, 256>>>(nMH4);

    const long long tot = (long long)E * 32;  // one warp per edge
    edge_kernel<<<(unsigned)((tot + 255) / 256), 256>>>(snd, rcv, ew, q_out, E);

    lstm_kernel<<<(nMH4 + 255) / 256, 256>>>(cp, h_out, c_out, nMH4);
}

// round 13
// speedup vs baseline: 1.5639x; 1.5639x over previous
#include <cuda_runtime.h>
#include <cuda_bf16.h>
#include <math.h>

#define H 128
#define IN_SZ 64
#define MAX_NODES 50000
#define GATES 512

// ---------------- scratch (no allocations allowed) ----------------
__device__ float g_A[(size_t)MAX_NODES * H];         // h @ W_eg[:, :128].T + b_eg
__device__ float g_B[(size_t)MAX_NODES * H];         // h @ W_eg[:, 128:].T
__device__ float g_up[(size_t)MAX_NODES * H];        // upstream_q accumulator
__device__ float g_gates[(size_t)MAX_NODES * GATES]; // pre-activation LSTM gates

__device__ __forceinline__ float sigmoidf_(float x) {
    return 1.0f / (1.0f + __expf(-x));
}

// ---------------- TF32 MMA helpers ----------------
__device__ __forceinline__ unsigned f2tf(float f) {
    unsigned u;
    asm("cvt.rna.tf32.f32 %0, %1;" : "=r"(u) : "f"(f));
    return u;
}
__device__ __forceinline__ uint4 cvt4(float4 v) {
    uint4 u;
    u.x = f2tf(v.x); u.y = f2tf(v.y); u.z = f2tf(v.z); u.w = f2tf(v.w);
    return u;
}
__device__ __forceinline__ void mma8(float* c, const unsigned* a, const unsigned* b) {
    asm volatile(
        "mma.sync.aligned.m16n8k8.row.col.f32.tf32.tf32.f32 "
        "{%0,%1,%2,%3}, {%4,%5,%6,%7}, {%8,%9}, {%0,%1,%2,%3};"
        : "+f"(c[0]), "+f"(c[1]), "+f"(c[2]), "+f"(c[3])
        : "r"(a[0]), "r"(a[1]), "r"(a[2]), "r"(a[3]), "r"(b[0]), "r"(b[1]));
}

// =====================================================================
// TF32 tensor-core GEMM: CTA tile 64(M) x 128(N) x 16(K), 256 threads.
// 8 warps in 2(m) x 4(n) grid -> warp tile 32x32 (2 m-atoms x 4 n-atoms
// of m16n8k8). Smem rows padded to 20 uints: fragment loads
// (row = base+gid, col = ka+tig) hit banks 20*gid + tig -> conflict-free.
// Double-buffered; fp32->tf32 conversion at smem store.
// =====================================================================
#define SPAD 20

#define TC_COMPUTE(bb)                                                     \
    _Pragma("unroll")                                                      \
    for (int ka = 0; ka < 16; ka += 8) {                                   \
        unsigned af[2][4], bf[4][2];                                       \
        _Pragma("unroll")                                                  \
        for (int mi = 0; mi < 2; ++mi) {                                   \
            const int ar = warp_m * 32 + mi * 16;                          \
            af[mi][0] = As[bb][ar + gid][ka + tig];                        \
            af[mi][1] = As[bb][ar + 8 + gid][ka + tig];                    \
            af[mi][2] = As[bb][ar + gid][ka + tig + 4];                    \
            af[mi][3] = As[bb][ar + 8 + gid][ka + tig + 4];                \
        }                                                                  \
        _Pragma("unroll")                                                  \
        for (int ni = 0; ni < 4; ++ni) {                                   \
            const int br = warp_n * 32 + ni * 8;                           \
            bf[ni][0] = Ws[bb][br + gid][ka + tig];                        \
            bf[ni][1] = Ws[bb][br + gid][ka + tig + 4];                    \
        }                                                                  \
        _Pragma("unroll")                                                  \
        for (int mi = 0; mi < 2; ++mi)                                     \
            _Pragma("unroll")                                              \
            for (int ni = 0; ni < 4; ++ni)                                 \
                mma8(acc[mi][ni], af[mi], bf[ni]);                         \
    }

#define TC_STORE(bb)                                                       \
    do {                                                                   \
        *(uint4*)&As[bb][lrow][lc4]      = cvt4(va0);                      \
        *(uint4*)&Ws[bb][lrow][lc4]      = cvt4(vw0);                      \
        *(uint4*)&Ws[bb][lrow + 64][lc4] = cvt4(vw1);                      \
    } while (0)

// ---------------- GEMM 1: [q | A | B] = h @ [Wq | W1 | W2].T ----------------
// M x 384, K = 128 (8 k-chunks). blockIdx.y = slab: 0->q, 1->A, 2->B.
__global__ __launch_bounds__(256, 2)
void gemm_qab_tc(const float* __restrict__ h,
                 const float* __restrict__ Wq,
                 const float* __restrict__ bq,
                 const float* __restrict__ Weg,
                 const float* __restrict__ beg,
                 float* __restrict__ qout,
                 int M) {
    __shared__ unsigned As[2][64][SPAD];
    __shared__ unsigned Ws[2][128][SPAD];

    const int t    = threadIdx.x;
    const int wid  = t >> 5, lane = t & 31;
    const int gid  = lane >> 2, tig = lane & 3;
    const int warp_m = wid & 1, warp_n = wid >> 1;
    const int row0 = blockIdx.x * 64;
    const int slab = blockIdx.y;

    const int lrow = t >> 2;          // 0..63
    const int lc4  = (t & 3) * 4;     // 0,4,8,12

    const int  arow = row0 + lrow;
    const bool aok  = (arow < M);
    const float* ap = h + (size_t)arow * H;

    const float* w0;
    if (slab == 0) w0 = Wq  + (size_t)lrow * H;
    else           w0 = Weg + (size_t)lrow * 256 + (slab == 2 ? 128 : 0);
    const float* w1 = w0 + (size_t)64 * (slab == 0 ? H : 256);

    float acc[2][4][4] = {};

    float4 va0 = make_float4(0.f, 0.f, 0.f, 0.f), vw0, vw1;
    if (aok) va0 = *(const float4*)&ap[lc4];
    vw0 = *(const float4*)&w0[lc4];
    vw1 = *(const float4*)&w1[lc4];
    TC_STORE(0);
    __syncthreads();

    int buf = 0;
    #pragma unroll
    for (int kt = 0; kt < 8; ++kt) {
        const bool more = (kt + 1 < 8);
        if (more) {
            const int kb = (kt + 1) * 16 + lc4;
            va0 = aok ? *(const float4*)&ap[kb] : make_float4(0.f, 0.f, 0.f, 0.f);
            vw0 = *(const float4*)&w0[kb];
            vw1 = *(const float4*)&w1[kb];
        }
        if (buf == 0) { TC_COMPUTE(0); } else { TC_COMPUTE(1); }
        if (more) {
            if (buf == 0) TC_STORE(1); else TC_STORE(0);
            __syncthreads();
            buf ^= 1;
        }
    }

    // epilogue: c0/c1 -> row r, cols n/n+1; c2/c3 -> row r+8
    const float* bias  = (slab == 0) ? bq : (slab == 1 ? beg : nullptr);
    float*       obase = (slab == 0) ? qout : (slab == 1 ? g_A : g_B);
    #pragma unroll
    for (int mi = 0; mi < 2; ++mi) {
        const int r = row0 + warp_m * 32 + mi * 16 + gid;
        #pragma unroll
        for (int ni = 0; ni < 4; ++ni) {
            const int n = warp_n * 32 + ni * 8 + tig * 2;
            const float b0v = bias ? bias[n]     : 0.f;
            const float b1v = bias ? bias[n + 1] : 0.f;
            const float* c = acc[mi][ni];
            if (r < M)
                *(float2*)&obase[(size_t)r * H + n] =
                    make_float2(c[0] + b0v, c[1] + b1v);
            if (r + 8 < M)
                *(float2*)&obase[(size_t)(r + 8) * H + n] =
                    make_float2(c[2] + b0v, c[3] + b1v);
        }
    }
}

// ---------------- GEMM 2: gates = x @ W_ih.T + b_ih + h @ W_hh.T -------------
// M x 512, K = 192 (12 k-chunks; first 4 from x/W_ih, rest from h/W_hh).
__global__ __launch_bounds__(256, 2)
void gemm_gates_tc(const float* __restrict__ x,
                   const float* __restrict__ h,
                   const float* __restrict__ Wih,
                   const float* __restrict__ bih,
                   const float* __restrict__ Whh,
                   int M) {
    __shared__ unsigned As[2][64][SPAD];
    __shared__ unsigned Ws[2][128][SPAD];

    const int t    = threadIdx.x;
    const int wid  = t >> 5, lane = t & 31;
    const int gid  = lane >> 2, tig = lane & 3;
    const int warp_m = wid & 1, warp_n = wid >> 1;
    const int row0 = blockIdx.x * 64;
    const int n0   = blockIdx.y * 128;   // 0..511 in 128-col slabs

    const int lrow = t >> 2;
    const int lc4  = (t & 3) * 4;

    const int  arow = row0 + lrow;
    const bool aok  = (arow < M);
    const float* xp = x + (size_t)arow * IN_SZ;
    const float* hp = h + (size_t)arow * H;
    const int gn0 = n0 + lrow;
    const int gn1 = gn0 + 64;

    float acc[2][4][4] = {};

    // chunk 0 (kb = 0 < IN_SZ)
    float4 va0 = make_float4(0.f, 0.f, 0.f, 0.f), vw0, vw1;
    if (aok) va0 = *(const float4*)&xp[lc4];
    vw0 = *(const float4*)&Wih[(size_t)gn0 * IN_SZ + lc4];
    vw1 = *(const float4*)&Wih[(size_t)gn1 * IN_SZ + lc4];
    TC_STORE(0);
    __syncthreads();

    int buf = 0;
    #pragma unroll
    for (int kt = 0; kt < 12; ++kt) {
        const bool more = (kt + 1 < 12);
        if (more) {
            const int kb = (kt + 1) * 16;   // multiple of 16; never straddles 64
            if (kb < IN_SZ) {
                va0 = aok ? *(const float4*)&xp[kb + lc4] : make_float4(0.f,0.f,0.f,0.f);
                vw0 = *(const float4*)&Wih[(size_t)gn0 * IN_SZ + kb + lc4];
                vw1 = *(const float4*)&Wih[(size_t)gn1 * IN_SZ + kb + lc4];
            } else {
                const int kh = kb - IN_SZ;
                va0 = aok ? *(const float4*)&hp[kh + lc4] : make_float4(0.f,0.f,0.f,0.f);
                vw0 = *(const float4*)&Whh[(size_t)gn0 * H + kh + lc4];
                vw1 = *(const float4*)&Whh[(size_t)gn1 * H + kh + lc4];
            }
        }
        if (buf == 0) { TC_COMPUTE(0); } else { TC_COMPUTE(1); }
        if (more) {
            if (buf == 0) TC_STORE(1); else TC_STORE(0);
            __syncthreads();
            buf ^= 1;
        }
    }

    #pragma unroll
    for (int mi = 0; mi < 2; ++mi) {
        const int r = row0 + warp_m * 32 + mi * 16 + gid;
        #pragma unroll
        for (int ni = 0; ni < 4; ++ni) {
            const int n = n0 + warp_n * 32 + ni * 8 + tig * 2;
            const float b0v = bih[n];
            const float b1v = bih[n + 1];
            const float* c = acc[mi][ni];
            if (r < M)
                *(float2*)&g_gates[(size_t)r * GATES + n] =
                    make_float2(c[0] + b0v, c[1] + b1v);
            if (r + 8 < M)
                *(float2*)&g_gates[(size_t)(r + 8) * GATES + n] =
                    make_float2(c[2] + b0v, c[3] + b1v);
        }
    }
}

// ---------------- zero upstream accumulator (vectorized) ----------------
__global__ void zero_up(int n4) {  // n4 = M*H/4
    int idx = blockIdx.x * blockDim.x + threadIdx.x;
    if (idx < n4) ((float4*)g_up)[idx] = make_float4(0.f, 0.f, 0.f, 0.f);
}

// ---------------- edge kernel: gate, message, vectorized scatter-add ---------
// One warp per edge; each lane handles 4 channels via float4.
__global__ void edge_kernel(const int* __restrict__ snd,
                            const int* __restrict__ rcv,
                            const float* __restrict__ ew,
                            const float* __restrict__ q,
                            int E) {
    const int idx  = blockIdx.x * blockDim.x + threadIdx.x;
    const int e    = idx >> 5;
    const int lane = idx & 31;
    if (e >= E) return;

    const int s   = __ldg(&snd[e]);
    const int r   = __ldg(&rcv[e]);
    const float w = __ldg(&ew[e]);

    const size_t so = (size_t)s * 32 + lane;   // in float4 units
    const size_t ro = (size_t)r * 32 + lane;

    const float4 a  = ((const float4*)g_A)[so];
    const float4 b  = ((const float4*)g_B)[ro];
    const float4 qv = ((const float4*)q)[so];

    float4 m;
    m.x = qv.x * w * sigmoidf_(a.x + b.x);
    m.y = qv.y * w * sigmoidf_(a.y + b.y);
    m.z = qv.z * w * sigmoidf_(a.z + b.z);
    m.w = qv.w * w * sigmoidf_(a.w + b.w);

    float* dst = g_up + ro * 4;
#if defined(__CUDA_ARCH__) && (__CUDA_ARCH__ >= 900)
    asm volatile("red.global.add.v4.f32 [%0], {%1, %2, %3, %4};"
                 :: "l"(dst), "f"(m.x), "f"(m.y), "f"(m.z), "f"(m.w)
                 : "memory");
#else
    atomicAdd(dst + 0, m.x);
    atomicAdd(dst + 1, m.y);
    atomicAdd(dst + 2, m.z);
    atomicAdd(dst + 3, m.w);
#endif
}

// ---------------- final LSTM elementwise (vectorized) ----------------
__global__ void lstm_kernel(const float* __restrict__ c_prev,
                            float* __restrict__ h_out,
                            float* __restrict__ c_out,
                            int n4) {  // n4 = M*H/4
    int idx = blockIdx.x * blockDim.x + threadIdx.x;
    if (idx >= n4) return;
    const int node = idx >> 5;       // 32 float4s per node
    const int c4   = idx & 31;
    const size_t gbase = (size_t)node * 128;  // 4H floats = 128 float4s
    const float4 gi = ((const float4*)g_gates)[gbase + c4];
    const float4 gf = ((const float4*)g_gates)[gbase + 32 + c4];
    const float4 gg = ((const float4*)g_gates)[gbase + 64 + c4];
    const float4 go = ((const float4*)g_gates)[gbase + 96 + c4];
    const float4 cp = ((const float4*)c_prev)[idx];
    const float4 up = ((const float4*)g_up)[idx];

    float4 hn, cn;
    {
        float i = sigmoidf_(gi.x), f = sigmoidf_(gf.x), g = tanhf(gg.x), o = sigmoidf_(go.x);
        cn.x = f * (cp.x + up.x) + i * g;  hn.x = o * tanhf(cn.x);
    }
    {
        float i = sigmoidf_(gi.y), f = sigmoidf_(gf.y), g = tanhf(gg.y), o = sigmoidf_(go.y);
        cn.y = f * (cp.y + up.y) + i * g;  hn.y = o * tanhf(cn.y);
    }
    {
        float i = sigmoidf_(gi.z), f = sigmoidf_(gf.z), g = tanhf(gg.z), o = sigmoidf_(go.z);
        cn.z = f * (cp.z + up.z) + i * g;  hn.z = o * tanhf(cn.z);
    }
    {
        float i = sigmoidf_(gi.w), f = sigmoidf_(gf.w), g = tanhf(gg.w), o = sigmoidf_(go.w);
        cn.w = f * (cp.w + up.w) + i * g;  hn.w = o * tanhf(cn.w);
    }
    ((float4*)h_out)[idx] = hn;
    ((float4*)c_out)[idx] = cn;
}

// ---------------- launch ----------------
extern "C" void kernel_launch(void* const* d_in, const int* in_sizes, int n_in,
                              void* d_out, int out_size) {
    const float* x   = (const float*)d_in[0];
    const float* h   = (const float*)d_in[1];
    const float* cp  = (const float*)d_in[2];
    const int*   snd = (const int*)d_in[3];
    const int*   rcv = (const int*)d_in[4];
    const float* ew  = (const float*)d_in[5];
    // d_in[6] = num_nodes (scalar, unused; derived from sizes)
    const float* Wih = (const float*)d_in[7];
    const float* bih = (const float*)d_in[8];
    const float* Whh = (const float*)d_in[9];
    const float* Wq  = (const float*)d_in[10];
    const float* bq  = (const float*)d_in[11];
    const float* Weg = (const float*)d_in[12];
    const float* beg = (const float*)d_in[13];

    const int M = in_sizes[1] / H;       // 50000
    const int E = in_sizes[3];           // 800000

    float* out   = (float*)d_out;
    float* h_out = out;
    float* c_out = out + (size_t)M * H;
    float* q_out = out + (size_t)2 * M * H;

    const int nMH  = M * H;
    const int nMH4 = nMH / 4;

    // node GEMMs (must precede edge/lstm)
    dim3 g1((M + 63) / 64, 3);
    gemm_qab_tc<<<g1, 256>>>(h, Wq, bq, Weg, beg, q_out, M);

    dim3 g2((M + 63) / 64, 4);
    gemm_gates_tc<<<g2, 256>>>(x, h, Wih, bih, Whh, M);

    zero_up<<<(nMH4 + 255) / 256, 256>>>(nMH4);

    const long long tot = (long long)E * 32;  // one warp per edge
    edge_kernel<<<(unsigned)((tot + 255) / 256), 256>>>(snd, rcv, ew, q_out, E);

    lstm_kernel<<<(nMH4 + 255) / 256, 256>>>(cp, h_out, c_out, nMH4);
}